// round 3
// baseline (speedup 1.0000x reference)
#include <cuda_runtime.h>
#include <cstdint>

// Problem constants
#define T_DIM 8
#define C_DIM 4
#define NMAPS (T_DIM * C_DIM)        // 32
#define H_DIM 1024
#define W_DIM 1024
#define NUM_GRID 16
#define NCELLS (NUM_GRID * NUM_GRID) // 256
#define THRESH 0.65f
#define NUM_FG 40
#define NUM_BG 1
#define MAX_PTS 42
#define BLOCKS_PER_MAP 16            // 16 blocks/map, 8 warps, 2 cells per warp

// Scratch (__device__ globals; no allocations allowed)
__device__ unsigned long long g_cellpack[NMAPS * NCELLS];
__device__ unsigned long long g_blockmin[NMAPS * BLOCKS_PER_MAP];
__device__ int g_ctr[NMAPS];         // self-resetting -> graph-replay safe

// Process one 64x64 cell with a warp. Value-only FMNMX chains + deferred
// argmax/argmin recovery (re-read of the single flagged chunk).
// Returns (maxv,maxi,minv,mini) in lane-uniform registers.
__device__ __forceinline__ void process_cell(
    const float* __restrict__ base, int cy, int cx, int lane,
    float& omaxv, unsigned& omaxi, float& ominv, unsigned& omini)
{
    const int rowsel = lane >> 4;
    const int col    = (cx << 6) + ((lane & 15) << 2);
    const int row0   = (cy << 6) + rowsel;

    const float INF = __int_as_float(0x7f800000);
    float cellmax = -INF, cellmin = INF;
    int   maxChunk = 0, minChunk = 0;

    #pragma unroll
    for (int c = 0; c < 4; ++c) {
        float4 v[8];
        #pragma unroll
        for (int j = 0; j < 8; ++j) {
            const int row = row0 + ((c * 8 + j) << 1);
            v[j] = *reinterpret_cast<const float4*>(base + ((unsigned)row << 10) + col);
        }
        // 4 independent component chains per direction (pure FMNMX)
        float mxx = v[0].x, mxy = v[0].y, mxz = v[0].z, mxw = v[0].w;
        float mnx = v[0].x, mny = v[0].y, mnz = v[0].z, mnw = v[0].w;
        #pragma unroll
        for (int j = 1; j < 8; ++j) {
            mxx = fmaxf(mxx, v[j].x); mxy = fmaxf(mxy, v[j].y);
            mxz = fmaxf(mxz, v[j].z); mxw = fmaxf(mxw, v[j].w);
            mnx = fminf(mnx, v[j].x); mny = fminf(mny, v[j].y);
            mnz = fminf(mnz, v[j].z); mnw = fminf(mnw, v[j].w);
        }
        const float cmax = fmaxf(fmaxf(mxx, mxy), fmaxf(mxz, mxw));
        const float cmin = fminf(fminf(mnx, mny), fminf(mnz, mnw));
        // strict compare keeps EARLIEST chunk achieving the lane extreme
        maxChunk = (cmax > cellmax) ? c : maxChunk;
        cellmax  = fmaxf(cellmax, cmax);
        minChunk = (cmin < cellmin) ? c : minChunk;
        cellmin  = fminf(cellmin, cmin);
    }

    // warp value reduction (all lanes get the result)
    float V = cellmax, Wm = cellmin;
    #pragma unroll
    for (int o = 16; o > 0; o >>= 1) {
        V  = fmaxf(V,  __shfl_xor_sync(0xffffffffu, V,  o));
        Wm = fminf(Wm, __shfl_xor_sync(0xffffffffu, Wm, o));
    }

    // deferred argmax: re-read flagged chunk (earliest element bit-equal to V)
    unsigned candMax = 0xffffffffu;
    if (cellmax == V) {
        for (int j = 0; j < 8; ++j) {
            const int row = row0 + ((maxChunk * 8 + j) << 1);
            const unsigned idx = ((unsigned)row << 10) + (unsigned)col;
            const float4 v = *reinterpret_cast<const float4*>(base + idx);
            if (v.x == V) { candMax = idx;     break; }
            if (v.y == V) { candMax = idx + 1; break; }
            if (v.z == V) { candMax = idx + 2; break; }
            if (v.w == V) { candMax = idx + 3; break; }
        }
    }
    unsigned candMin = 0xffffffffu;
    if (cellmin == Wm) {
        for (int j = 0; j < 8; ++j) {
            const int row = row0 + ((minChunk * 8 + j) << 1);
            const unsigned idx = ((unsigned)row << 10) + (unsigned)col;
            const float4 v = *reinterpret_cast<const float4*>(base + idx);
            if (v.x == Wm) { candMin = idx;     break; }
            if (v.y == Wm) { candMin = idx + 1; break; }
            if (v.z == Wm) { candMin = idx + 2; break; }
            if (v.w == Wm) { candMin = idx + 3; break; }
        }
    }
    // min-index reduction across lanes (non-candidates contribute ~0u)
    #pragma unroll
    for (int o = 16; o > 0; o >>= 1) {
        candMax = min(candMax, __shfl_xor_sync(0xffffffffu, candMax, o));
        candMin = min(candMin, __shfl_xor_sync(0xffffffffu, candMin, o));
    }
    omaxv = V; omaxi = candMax; ominv = Wm; omini = candMin;
}

// ---------------------------------------------------------------------------
// Fused kernel. grid = NMAPS*16 blocks of 256 threads; each warp handles
// 2 cells. Last block per map runs selection + output assembly.
// ---------------------------------------------------------------------------
__global__ __launch_bounds__(256, 4) void k_fused(const float* __restrict__ sims,
                                                  const int* __restrict__ osz,
                                                  float* __restrict__ out,
                                                  int write_nums, int nums_off) {
    const int b    = blockIdx.x;           // 0..511
    const int m    = b >> 4;               // map id
    const int binm = b & 15;               // block within map
    const int warp = threadIdx.x >> 5;
    const int lane = threadIdx.x & 31;

    const float* __restrict__ base = sims + (size_t)m * (H_DIM * W_DIM);

    unsigned long long wminkey = ~0ULL;
    #pragma unroll
    for (int cc = 0; cc < 2; ++cc) {
        const int cid = (binm << 4) + (warp << 1) + cc;   // 0..255
        float maxv, minv; unsigned maxi, mini;
        process_cell(base, cid >> 4, cid & 15, lane, maxv, maxi, minv, mini);
        if (lane == 0) {
            g_cellpack[m * NCELLS + cid] =
                ((unsigned long long)__float_as_uint(maxv) << 32) |
                (unsigned long long)maxi;
            const unsigned long long k =
                ((unsigned long long)(__float_as_uint(minv) ^ 0x80000000u) << 32) |
                (unsigned long long)mini;
            wminkey = min(wminkey, k);
        }
    }

    __shared__ unsigned long long sminkey[8];
    if (lane == 0) sminkey[warp] = wminkey;
    __syncthreads();

    __shared__ int s_last;
    if (threadIdx.x == 0) {
        unsigned long long k = sminkey[0];
        #pragma unroll
        for (int j = 1; j < 8; ++j) k = min(k, sminkey[j]);
        g_blockmin[m * BLOCKS_PER_MAP + binm] = k;
        __threadfence();                          // publish cellpack + blockmin
        const int c = atomicAdd(&g_ctr[m], 1);
        s_last = (c == BLOCKS_PER_MAP - 1);
        if (s_last) g_ctr[m] = 0;                 // self-reset for graph replays
    }
    __syncthreads();
    if (!s_last) return;

    // ======================= selection phase (last block) ==================
    const int tid = threadIdx.x;                  // == cell id

    __shared__ float    sval[NCELLS];
    __shared__ unsigned sidx[NCELLS];
    __shared__ unsigned long long s_mink;

    const unsigned long long p = g_cellpack[m * NCELLS + tid];
    const float    v   = __uint_as_float((unsigned)(p >> 32));
    const unsigned idx = (unsigned)p;
    sval[tid] = v;
    sidx[tid] = idx;

    if (tid < 32) {                               // reduce the 16 block mins
        unsigned long long k = (tid < BLOCKS_PER_MAP)
            ? g_blockmin[m * BLOCKS_PER_MAP + tid] : ~0ULL;
        #pragma unroll
        for (int o = 8; o > 0; o >>= 1)
            k = min(k, __shfl_down_sync(0xffffffffu, k, o));
        if (tid == 0) s_mink = k;
    }

    float* __restrict__ orow = out + (size_t)m * (MAX_PTS * 4);
    if (tid < MAX_PTS) {
        reinterpret_cast<float4*>(orow)[tid] = make_float4(0.f, 0.f, 0.f, 0.f);
    }

    const bool valid   = (v > THRESH);
    const int  count   = __syncthreads_count(valid);   // barrier: sval/zero done
    const int  n_valid = count < NUM_FG ? count : NUM_FG;
    const bool any_fg  = (count > 0);

    const int   t  = m / C_DIM;
    const float sx = (float)osz[t * 2 + 1] / (float)W_DIM;
    const float sy = (float)osz[t * 2 + 0] / (float)H_DIM;

    // rank = #cells strictly better: (score desc, cell-id asc) == stable argsort
    const float NEGINF = -__int_as_float(0x7f800000);
    const float effv = valid ? v : NEGINF;
    int rank = 0;
    #pragma unroll 8
    for (int j = 0; j < NCELLS; ++j) {
        const float jv = sval[j];
        const float ej = (jv > THRESH) ? jv : NEGINF;
        rank += (int)((ej > effv) || (ej == effv && j < tid));
    }

    if (any_fg) {
        if (valid && rank < NUM_FG) {
            const float px = (float)(idx & (W_DIM - 1));
            const float py = (float)(idx >> 10);
            reinterpret_cast<float4*>(orow)[rank] =
                make_float4(px * sx, py * sy, v, 1.0f);
        }
    } else if (tid == 0) {
        // fallback: global argmax (value desc, idx asc) over cell maxima
        float    bv = sval[0];
        unsigned bi = sidx[0];
        for (int j = 1; j < NCELLS; ++j) {
            if (sval[j] > bv || (sval[j] == bv && sidx[j] < bi)) { bv = sval[j]; bi = sidx[j]; }
        }
        const float px = (float)(bi & (W_DIM - 1));
        const float py = (float)(bi >> 10);
        reinterpret_cast<float4*>(orow)[0] = make_float4(px * sx, py * sy, bv, 1.0f);
    }

    const int fg_count = any_fg ? n_valid : 1;
    if (tid == 0) {
        const unsigned long long k = s_mink;
        const float    bvv = __uint_as_float(((unsigned)(k >> 32)) ^ 0x80000000u);
        const unsigned bii = (unsigned)k;
        const float px = (float)(bii & (W_DIM - 1));
        const float py = (float)(bii >> 10);
        reinterpret_cast<float4*>(orow)[fg_count] =
            make_float4(px * sx, py * sy, bvv, 0.0f);
        if (write_nums)
            out[nums_off + m] = (float)(fg_count + NUM_BG);
    }
}

extern "C" void kernel_launch(void* const* d_in, const int* in_sizes, int n_in,
                              void* d_out, int out_size) {
    const float* sims = (const float*)d_in[0];
    // d_in[1] = category_ids (unused by the reference computation)
    const int* osz = (const int*)d_in[2];
    float* out = (float*)d_out;

    const int pts_elems = NMAPS * MAX_PTS * 4;                 // 5376
    const int write_nums = (out_size >= pts_elems + NMAPS) ? 1 : 0;

    k_fused<<<NMAPS * BLOCKS_PER_MAP, 256>>>(sims, osz, out, write_nums, pts_elems);
}

// round 4
// speedup vs baseline: 1.2814x; 1.2814x over previous
#include <cuda_runtime.h>
#include <cstdint>

// Problem constants
#define T_DIM 8
#define C_DIM 4
#define NMAPS (T_DIM * C_DIM)        // 32
#define H_DIM 1024
#define W_DIM 1024
#define NUM_GRID 16
#define NCELLS (NUM_GRID * NUM_GRID) // 256
#define THRESH 0.65f
#define NUM_FG 40
#define NUM_BG 1
#define MAX_PTS 42
#define BLOCKS_PER_MAP 32            // 8 warps/block, 1 cell per warp

// Scratch (__device__ globals; no allocations allowed)
__device__ unsigned long long g_cellpack[NMAPS * NCELLS];
__device__ unsigned long long g_blockmin[NMAPS * BLOCKS_PER_MAP];
__device__ int g_ctr[NMAPS];         // self-resetting -> graph-replay safe

// ---------------------------------------------------------------------------
// Fused kernel: per-cell max/argmax + per-map min, then the LAST block of
// each map performs selection + output assembly.
// grid = NMAPS * 32 blocks (each block: 8 warps = 8 cells), block = 256 thr.
// Inner loop: 4 front-batched LDG.128 per iteration (MLP), branchy
// earliest-index updates (bit-exact, strict >/< keeps first occurrence).
// ---------------------------------------------------------------------------
__global__ __launch_bounds__(256, 6) void k_fused(const float* __restrict__ sims,
                                                  const int* __restrict__ osz,
                                                  float* __restrict__ out,
                                                  int write_nums, int nums_off) {
    const int b    = blockIdx.x;          // 0..1023
    const int m    = b >> 5;              // map id
    const int binm = b & 31;              // block within map
    const int warp = threadIdx.x >> 5;
    const int lane = threadIdx.x & 31;
    const int cid  = (binm << 3) + warp;  // 0..255
    const int cy   = cid >> 4;
    const int cx   = cid & 15;

    const float* __restrict__ base = sims + (size_t)m * (H_DIM * W_DIM);
    const int rowsel = lane >> 4;                     // 0/1: which of 2 rows
    const int col    = (cx << 6) + ((lane & 15) << 2);
    // lane's first element index; rows advance by 2 per float4 step
    const unsigned idx0 = (((unsigned)((cy << 6) + rowsel)) << 10) + (unsigned)col;

    float    minv = __int_as_float(0x7f800000);       // +inf
    float    maxv = -minv;
    unsigned maxi = 0u, mini = 0u;

    // 32 float4 per lane, 8 iterations x 4 front-batched loads
    #pragma unroll
    for (int i = 0; i < 8; ++i) {
        const unsigned ib = idx0 + ((unsigned)i << 13);     // i*8 rows * 1024
        const float4 v0 = *reinterpret_cast<const float4*>(base + ib);
        const float4 v1 = *reinterpret_cast<const float4*>(base + ib + (2u << 10));
        const float4 v2 = *reinterpret_cast<const float4*>(base + ib + (4u << 10));
        const float4 v3 = *reinterpret_cast<const float4*>(base + ib + (6u << 10));

        // process in increasing-index order; strict cmp keeps earliest index
        #define UPD(v, off) do {                                             \
            const unsigned _i = ib + (unsigned)(off);                        \
            if ((v).x > maxv) { maxv = (v).x; maxi = _i;     }               \
            if ((v).y > maxv) { maxv = (v).y; maxi = _i + 1; }               \
            if ((v).z > maxv) { maxv = (v).z; maxi = _i + 2; }               \
            if ((v).w > maxv) { maxv = (v).w; maxi = _i + 3; }               \
            if ((v).x < minv) { minv = (v).x; mini = _i;     }               \
            if ((v).y < minv) { minv = (v).y; mini = _i + 1; }               \
            if ((v).z < minv) { minv = (v).z; mini = _i + 2; }               \
            if ((v).w < minv) { minv = (v).w; mini = _i + 3; }               \
        } while (0)
        UPD(v0, 0);
        UPD(v1, 2u << 10);
        UPD(v2, 4u << 10);
        UPD(v3, 6u << 10);
        #undef UPD
    }

    // warp lexicographic reduce: (max val, min idx) / (min val, min idx)
    #pragma unroll
    for (int o = 16; o > 0; o >>= 1) {
        float    ov = __shfl_down_sync(0xffffffffu, maxv, o);
        unsigned oi = __shfl_down_sync(0xffffffffu, maxi, o);
        if (ov > maxv || (ov == maxv && oi < maxi)) { maxv = ov; maxi = oi; }
        float    nv = __shfl_down_sync(0xffffffffu, minv, o);
        unsigned ni = __shfl_down_sync(0xffffffffu, mini, o);
        if (nv < minv || (nv == minv && ni < mini)) { minv = nv; mini = ni; }
    }

    __shared__ unsigned long long sminkey[8];
    if (lane == 0) {
        g_cellpack[m * NCELLS + cid] =
            ((unsigned long long)__float_as_uint(maxv) << 32) | (unsigned long long)maxi;
        // orderable transform (values are non-negative floats): bits ^ 0x80000000
        sminkey[warp] =
            ((unsigned long long)(__float_as_uint(minv) ^ 0x80000000u) << 32) |
            (unsigned long long)mini;
    }
    __syncthreads();

    __shared__ int s_last;
    if (threadIdx.x == 0) {
        unsigned long long k = sminkey[0];
        #pragma unroll
        for (int j = 1; j < 8; ++j) k = min(k, sminkey[j]);
        g_blockmin[m * BLOCKS_PER_MAP + binm] = k;
        __threadfence();                          // publish cellpack + blockmin
        const int c = atomicAdd(&g_ctr[m], 1);
        s_last = (c == BLOCKS_PER_MAP - 1);
        if (s_last) g_ctr[m] = 0;                 // self-reset for graph replays
    }
    __syncthreads();
    if (!s_last) return;

    // ======================= selection phase (last block) ==================
    const int tid = threadIdx.x;                  // == cell id

    __shared__ float    sval[NCELLS];
    __shared__ unsigned sidx[NCELLS];
    __shared__ unsigned long long s_mink;

    const unsigned long long p = g_cellpack[m * NCELLS + tid];
    const float    v   = __uint_as_float((unsigned)(p >> 32));
    const unsigned idx = (unsigned)p;
    sval[tid] = v;
    sidx[tid] = idx;

    if (tid < 32) {                               // reduce the 32 block mins
        unsigned long long k = g_blockmin[m * BLOCKS_PER_MAP + tid];
        #pragma unroll
        for (int o = 16; o > 0; o >>= 1)
            k = min(k, __shfl_down_sync(0xffffffffu, k, o));
        if (tid == 0) s_mink = k;
    }

    float* __restrict__ orow = out + (size_t)m * (MAX_PTS * 4);
    if (tid < MAX_PTS) {
        reinterpret_cast<float4*>(orow)[tid] = make_float4(0.f, 0.f, 0.f, 0.f);
    }

    const bool valid   = (v > THRESH);
    const int  count   = __syncthreads_count(valid);   // barrier: sval/zero done
    const int  n_valid = count < NUM_FG ? count : NUM_FG;
    const bool any_fg  = (count > 0);

    const int   t  = m / C_DIM;
    const float sx = (float)osz[t * 2 + 1] / (float)W_DIM;
    const float sy = (float)osz[t * 2 + 0] / (float)H_DIM;

    // rank = #cells strictly better: (score desc, cell-id asc) == stable argsort
    const float NEGINF = -__int_as_float(0x7f800000);
    const float effv = valid ? v : NEGINF;
    int rank = 0;
    #pragma unroll 8
    for (int j = 0; j < NCELLS; ++j) {
        const float jv = sval[j];
        const float ej = (jv > THRESH) ? jv : NEGINF;
        rank += (int)((ej > effv) || (ej == effv && j < tid));
    }

    if (any_fg) {
        if (valid && rank < NUM_FG) {
            const float px = (float)(idx & (W_DIM - 1));
            const float py = (float)(idx >> 10);
            reinterpret_cast<float4*>(orow)[rank] =
                make_float4(px * sx, py * sy, v, 1.0f);
        }
    } else if (tid == 0) {
        // fallback: global argmax (value desc, idx asc) over cell maxima
        float    bv = sval[0];
        unsigned bi = sidx[0];
        for (int j = 1; j < NCELLS; ++j) {
            if (sval[j] > bv || (sval[j] == bv && sidx[j] < bi)) { bv = sval[j]; bi = sidx[j]; }
        }
        const float px = (float)(bi & (W_DIM - 1));
        const float py = (float)(bi >> 10);
        reinterpret_cast<float4*>(orow)[0] = make_float4(px * sx, py * sy, bv, 1.0f);
    }

    const int fg_count = any_fg ? n_valid : 1;
    if (tid == 0) {
        const unsigned long long k = s_mink;
        const float    bvv = __uint_as_float(((unsigned)(k >> 32)) ^ 0x80000000u);
        const unsigned bii = (unsigned)k;
        const float px = (float)(bii & (W_DIM - 1));
        const float py = (float)(bii >> 10);
        reinterpret_cast<float4*>(orow)[fg_count] =
            make_float4(px * sx, py * sy, bvv, 0.0f);
        if (write_nums)
            out[nums_off + m] = (float)(fg_count + NUM_BG);
    }
}

extern "C" void kernel_launch(void* const* d_in, const int* in_sizes, int n_in,
                              void* d_out, int out_size) {
    const float* sims = (const float*)d_in[0];
    // d_in[1] = category_ids (unused by the reference computation)
    const int* osz = (const int*)d_in[2];
    float* out = (float*)d_out;

    const int pts_elems = NMAPS * MAX_PTS * 4;                 // 5376
    const int write_nums = (out_size >= pts_elems + NMAPS) ? 1 : 0;

    k_fused<<<NMAPS * BLOCKS_PER_MAP, 256>>>(sims, osz, out, write_nums, pts_elems);
}